// round 8
// baseline (speedup 1.0000x reference)
#include <cuda_runtime.h>

#define B_ 32
#define L_ 128
#define D_ 48
#define R_ 64
#define OUTSZ (B_*R_*D_)   // 98304
#define LSN 16             // 16 L-slices of 8 l
#define NGRP 32            // 4 bg x 8 rg

typedef unsigned long long ull;

__device__ float g_scratch[LSN * OUTSZ];   // 6.3 MB partials
__device__ int   g_cnt[NGRP];

#define PACK2(dst, lo, hi) \
    asm("mov.b64 %0, {%1, %2};" : "=l"(dst) : "r"(__float_as_uint(lo)), "r"(__float_as_uint(hi)))
#define UNPACK2(lo, hi, src) do { unsigned _a, _b; \
    asm("mov.b64 {%0, %1}, %2;" : "=r"(_a), "=r"(_b) : "l"(src)); \
    lo = __uint_as_float(_a); hi = __uint_as_float(_b); } while(0)
#define ADD2(d, a, b)  asm("add.rn.f32x2 %0, %1, %2;" : "=l"(d) : "l"(a), "l"(b))
#define MUL2(d, a, b)  asm("mul.rn.f32x2 %0, %1, %2;" : "=l"(d) : "l"(a), "l"(b))
#define FMA2ACC(acc, a, b) asm("fma.rn.f32x2 %0, %1, %2, %0;" : "+l"(acc) : "l"(a), "l"(b))
#define EX2(d, a)      asm("ex2.approx.ftz.f32 %0, %1;" : "=f"(d) : "f"(a))

__global__ __launch_bounds__(192, 2) void alnn_fused(
    const float* __restrict__ X, const float* __restrict__ T,
    const float* __restrict__ M, const float* __restrict__ DT,
    const float* __restrict__ P, const float* __restrict__ alpha,
    const float* __restrict__ w_t, const float* __restrict__ b_t,
    const float* __restrict__ w_v, const float* __restrict__ b_v,
    float* __restrict__ out)
{
    // Grid: 512 = 4 bg x 8 rg x 16 ls. Block: 192 = 4 lgroups x 48 d.
    const int c  = blockIdx.x;
    const int ls = c & 15;
    const int rg = (c >> 4) & 7;
    const int bg = c >> 7;

    const int tid = threadIdx.x;
    const int d = tid % D_;
    const int g = tid / D_;          // 0..3
    const int b0 = bg * 8;
    const int r0 = rg * 8;
    const int l0 = ls * 8 + g * 2;   // 2 l's per thread

    // -relu(alpha)*log2e per owned r (warp-uniform loads)
    float naa[8];
#pragma unroll
    for (int ri = 0; ri < 8; ri++)
        naa[ri] = -fmaxf(alpha[r0 + ri], 0.0f) * 1.4426950408889634f;

    ull acc2[4][8];
#pragma unroll
    for (int p = 0; p < 4; p++)
#pragma unroll
        for (int ri = 0; ri < 8; ri++) acc2[p][ri] = 0ull;

#pragma unroll 1
    for (int j = 0; j < 2; j++) {
        const int l = l0 + j;

        // Load inputs for 8 batches at (l,d), packed into 4 b-pairs
        ull xv2[4], xr2[4], tv2[4], mv2[4], dtv2[4], pv2[4];
#pragma unroll
        for (int p = 0; p < 4; p++) {
            const int i0 = ((b0 + 2*p) * L_ + l) * D_ + d;
            const int i1 = i0 + L_ * D_;
            const float x0 = X[i0], x1 = X[i1];
            PACK2(xv2[p], x0, x1);
            PACK2(xr2[p], fmaxf(x0, 0.0f), fmaxf(x1, 0.0f));
            PACK2(tv2[p],  T[i0],  T[i1]);
            PACK2(mv2[p],  M[i0],  M[i1]);
            PACK2(dtv2[p], DT[i0], DT[i1]);
            PACK2(pv2[p],  P[i0],  P[i1]);
        }

        const int wbase = (r0 * L_ + l) * D_ + d;
#pragma unroll
        for (int ri = 0; ri < 8; ri++) {
            const int wi = wbase + ri * (L_ * D_);
            const float* wt = w_t + (size_t)wi * 5;
            const float w0 = wt[0], w1 = wt[1], w2 = wt[2], w3 = wt[3], w4 = wt[4];
            const float bt5 = 5.0f * b_t[wi];
            const float wvh = 0.5f * w_v[wi];       // fold relu's 1/2 into w_v (exact)
            const float nrr = -(float)(r0 + ri) * (48.0f / 63.0f);
            ull w0_2, w1_2, w2_2, w3_2, w4_2, bt2, wv2, rr2, aa2;
            PACK2(w0_2, w0, w0);  PACK2(w1_2, w1, w1);
            PACK2(w2_2, w2, w2);  PACK2(w3_2, w3, w3);
            PACK2(w4_2, w4, w4);  PACK2(bt2, bt5, bt5);
            PACK2(wv2, wvh, wvh);
            PACK2(rr2, nrr, nrr);
            PACK2(aa2, naa[ri], naa[ri]);

#pragma unroll
            for (int p = 0; p < 4; p++) {
                ull d2, m2, k2, i2, s2, hs2;
                ADD2(d2, tv2[p], rr2);                 // t - ref
                MUL2(m2, d2, aa2);                     // -a*(t-ref)
                ull arg2 = m2 | 0x8000000080000000ull; // -|a*(t-ref)|
                float e0, e1, k0, k1;
                UNPACK2(e0, e1, arg2);
                EX2(k0, e0); EX2(k1, e1);
                PACK2(k2, k0, k1);
                MUL2(i2, xr2[p], k2);                  // relu(x)*kernel
                s2 = bt2;
                FMA2ACC(s2, w0_2, xv2[p]);
                FMA2ACC(s2, w1_2, i2);
                FMA2ACC(s2, w2_2, mv2[p]);
                FMA2ACC(s2, w3_2, dtv2[p]);
                FMA2ACC(s2, w4_2, pv2[p]);
                const ull ab2 = s2 & 0x7fffffff7fffffffull;
                ADD2(hs2, s2, ab2);                    // 2*relu(s)
                FMA2ACC(acc2[p][ri], wv2, hs2);        // (w_v/2)*2*relu(s)
            }
        }
    }

    // Intra-CTA reduction over the 4 l-groups, in 2 halves of 4 batches.
    __shared__ float sm[4 * 4 * 8 * D_];   // [g][bl][ri][d] = 24KB
    __shared__ int s_last;
#pragma unroll 1
    for (int h = 0; h < 2; h++) {
#pragma unroll
        for (int bl = 0; bl < 4; bl++) {
            const int p = h * 2 + (bl >> 1);
            const int hi = bl & 1;
#pragma unroll
            for (int ri = 0; ri < 8; ri++) {
                float lo, hv;
                UNPACK2(lo, hv, acc2[p][ri]);
                sm[((g * 4 + bl) * 8 + ri) * D_ + d] = hi ? hv : lo;
            }
        }
        __syncthreads();
#pragma unroll
        for (int k = 0; k < 8; k++) {
            const int idx = k * 192 + tid;             // 0..1535
            const float s = sm[idx] + sm[1536 + idx] + sm[2*1536 + idx] + sm[3*1536 + idx];
            const int dd = idx % D_;
            const int ri = (idx / D_) & 7;
            const int bl = idx / (8 * D_);
            const int b = b0 + h * 4 + bl;
            const int r = r0 + ri;
            g_scratch[ls * OUTSZ + (b * R_ + r) * D_ + dd] = s;
        }
        __syncthreads();
    }

    // ---- last CTA of (bg,rg) reduces the 16 l-slices and writes out ----
    __threadfence();
    if (tid == 0) {
        const int old = atomicAdd(&g_cnt[bg * 8 + rg], 1);
        s_last = (old == LSN - 1);
    }
    __syncthreads();
    if (!s_last) return;
    if (tid == 0) g_cnt[bg * 8 + rg] = 0;   // reset for next graph replay
    __threadfence();

    // 8b x 8r x 48d = 3072 outputs = 768 float4 quads; 4 per thread
#pragma unroll
    for (int s4 = 0; s4 < 4; s4++) {
        const int u  = tid + s4 * 192;      // 0..767
        const int dq = u % 12;
        const int r  = (u / 12) % 8 + r0;
        const int b  = u / 96 + b0;
        const int idx = (b * R_ + r) * D_ + dq * 4;
        const float4 bv = *(const float4*)&b_v[r * D_ + dq * 4];
        float4 s;
        s.x = 128.0f * bv.x; s.y = 128.0f * bv.y;
        s.z = 128.0f * bv.z; s.w = 128.0f * bv.w;
#pragma unroll
        for (int sl = 0; sl < LSN; sl++) {
            const float4 v = *(const float4*)&g_scratch[sl * OUTSZ + idx];
            s.x += v.x; s.y += v.y; s.z += v.z; s.w += v.w;
        }
        s.x = fmaxf(s.x, 0.0f); s.y = fmaxf(s.y, 0.0f);
        s.z = fmaxf(s.z, 0.0f); s.w = fmaxf(s.w, 0.0f);
        *(float4*)&out[idx] = s;
    }
}

extern "C" void kernel_launch(void* const* d_in, const int* in_sizes, int n_in,
                              void* d_out, int out_size)
{
    const float* X     = (const float*)d_in[0];
    const float* T     = (const float*)d_in[1];
    const float* M     = (const float*)d_in[2];
    const float* DT    = (const float*)d_in[3];
    const float* P     = (const float*)d_in[4];
    const float* alpha = (const float*)d_in[5];
    const float* w_t   = (const float*)d_in[6];
    const float* b_t   = (const float*)d_in[7];
    const float* w_v   = (const float*)d_in[8];
    const float* b_v   = (const float*)d_in[9];
    float* out = (float*)d_out;

    alnn_fused<<<512, 192>>>(X, T, M, DT, P, alpha, w_t, b_t, w_v, b_v, out);
}

// round 9
// speedup vs baseline: 1.1913x; 1.1913x over previous
#include <cuda_runtime.h>

#define B_ 32
#define L_ 128
#define D_ 48
#define R_ 64
#define OUTSZ (B_*R_*D_)   // 98304
#define NGRP 32            // 4 bg x 8 rg

typedef unsigned long long ull;

__device__ float g_scratch[8 * OUTSZ];   // 8 L-slices of (B,R,D)
__device__ int   g_cnt[NGRP];

#define PACK2(dst, lo, hi) \
    asm("mov.b64 %0, {%1, %2};" : "=l"(dst) : "r"(__float_as_uint(lo)), "r"(__float_as_uint(hi)))
#define UNPACK2(lo, hi, src) do { unsigned _a, _b; \
    asm("mov.b64 {%0, %1}, %2;" : "=r"(_a), "=r"(_b) : "l"(src)); \
    lo = __uint_as_float(_a); hi = __uint_as_float(_b); } while(0)
#define ADD2(d, a, b)  asm("add.rn.f32x2 %0, %1, %2;" : "=l"(d) : "l"(a), "l"(b))
#define MUL2(d, a, b)  asm("mul.rn.f32x2 %0, %1, %2;" : "=l"(d) : "l"(a), "l"(b))
#define FMA2ACC(acc, a, b) asm("fma.rn.f32x2 %0, %1, %2, %0;" : "+l"(acc) : "l"(a), "l"(b))
#define EX2(d, a)      asm("ex2.approx.ftz.f32 %0, %1;" : "=f"(d) : "f"(a))

__global__ __launch_bounds__(192, 2) void alnn_fused(
    const float* __restrict__ X, const float* __restrict__ T,
    const float* __restrict__ M, const float* __restrict__ DT,
    const float* __restrict__ P, const float* __restrict__ alpha,
    const float* __restrict__ w_t, const float* __restrict__ b_t,
    const float* __restrict__ w_v, const float* __restrict__ b_v,
    float* __restrict__ out)
{
    // Grid: 256 = 4 bg x 8 rg x 8 ls. Block: 192 = 4 lgroups x 48 d.
    const int c  = blockIdx.x;
    const int ls = c & 7;
    const int rg = (c >> 3) & 7;
    const int bg = c >> 6;

    const int tid = threadIdx.x;
    const int d = tid % D_;
    const int g = tid / D_;          // 0..3
    const int b0 = bg * 8;
    const int r0 = rg * 8;
    const int l0 = ls * 16 + g * 4;  // 4 l's per thread

    // -relu(alpha)*log2e per owned r (warp-uniform loads)
    float naa[8];
#pragma unroll
    for (int ri = 0; ri < 8; ri++)
        naa[ri] = -fmaxf(alpha[r0 + ri], 0.0f) * 1.4426950408889634f;

    ull acc2[4][8];
#pragma unroll
    for (int p = 0; p < 4; p++)
#pragma unroll
        for (int ri = 0; ri < 8; ri++) acc2[p][ri] = 0ull;

#pragma unroll 1
    for (int j = 0; j < 4; j++) {
        const int l = l0 + j;

        // Load inputs for 8 batches at (l,d), packed into 4 b-pairs (5 arrays, 40 regs)
        ull xv2[4], tv2[4], mv2[4], dtv2[4], pv2[4];
#pragma unroll
        for (int p = 0; p < 4; p++) {
            const int i0 = ((b0 + 2*p) * L_ + l) * D_ + d;
            const int i1 = i0 + L_ * D_;
            PACK2(xv2[p],  X[i0],  X[i1]);
            PACK2(tv2[p],  T[i0],  T[i1]);
            PACK2(mv2[p],  M[i0],  M[i1]);
            PACK2(dtv2[p], DT[i0], DT[i1]);
            PACK2(pv2[p],  P[i0],  P[i1]);
        }

        const int wbase = (r0 * L_ + l) * D_ + d;
#pragma unroll
        for (int ri = 0; ri < 8; ri++) {
            const int wi = wbase + ri * (L_ * D_);
            const float* wt = w_t + (size_t)wi * 5;
            const float w0 = wt[0], w2 = wt[2], w3 = wt[3], w4 = wt[4];
            const float w1h = 0.5f * wt[1];         // fold relu(x*k)'s 1/2 into w1 (exact)
            const float bt5 = 5.0f * b_t[wi];
            const float wvh = 0.5f * w_v[wi];       // fold relu(s)'s 1/2 into w_v (exact)
            const float nrr = -(float)(r0 + ri) * (48.0f / 63.0f);
            ull w0_2, w1_2, w2_2, w3_2, w4_2, bt2, wv2, rr2, aa2;
            PACK2(w0_2, w0, w0);    PACK2(w1_2, w1h, w1h);
            PACK2(w2_2, w2, w2);    PACK2(w3_2, w3, w3);
            PACK2(w4_2, w4, w4);    PACK2(bt2, bt5, bt5);
            PACK2(wv2, wvh, wvh);
            PACK2(rr2, nrr, nrr);
            PACK2(aa2, naa[ri], naa[ri]);

#pragma unroll
            for (int p = 0; p < 4; p++) {
                ull d2, m2, k2, xk2, i2, s2, hs2;
                ADD2(d2, tv2[p], rr2);                 // t - ref
                MUL2(m2, d2, aa2);                     // -a*(t-ref)
                ull arg2 = m2 | 0x8000000080000000ull; // -|a*(t-ref)|  (a>=0)
                float e0, e1, k0, k1;
                UNPACK2(e0, e1, arg2);
                EX2(k0, e0); EX2(k1, e1);
                PACK2(k2, k0, k1);
                MUL2(xk2, xv2[p], k2);                 // x*kernel
                const ull xab = xk2 & 0x7fffffff7fffffffull;
                ADD2(i2, xk2, xab);                    // 2*relu(x*kernel)
                s2 = bt2;
                FMA2ACC(s2, w0_2, xv2[p]);
                FMA2ACC(s2, w1_2, i2);                 // (w1/2)*2*relu(x*k)
                FMA2ACC(s2, w2_2, mv2[p]);
                FMA2ACC(s2, w3_2, dtv2[p]);
                FMA2ACC(s2, w4_2, pv2[p]);
                const ull ab2 = s2 & 0x7fffffff7fffffffull;
                ADD2(hs2, s2, ab2);                    // 2*relu(s)
                FMA2ACC(acc2[p][ri], wv2, hs2);        // (w_v/2)*2*relu(s)
            }
        }
    }

    // Intra-CTA reduction over the 4 l-groups, in 2 halves of 4 batches.
    __shared__ float sm[4 * 4 * 8 * D_];   // [g][bl][ri][d] = 24KB
    __shared__ int s_last;
#pragma unroll 1
    for (int h = 0; h < 2; h++) {
#pragma unroll
        for (int bl = 0; bl < 4; bl++) {
            const int p = h * 2 + (bl >> 1);
            const int hi = bl & 1;
#pragma unroll
            for (int ri = 0; ri < 8; ri++) {
                float lo, hv;
                UNPACK2(lo, hv, acc2[p][ri]);
                sm[((g * 4 + bl) * 8 + ri) * D_ + d] = hi ? hv : lo;
            }
        }
        __syncthreads();
#pragma unroll
        for (int k = 0; k < 8; k++) {
            const int idx = k * 192 + tid;             // 0..1535
            const float s = sm[idx] + sm[1536 + idx] + sm[2*1536 + idx] + sm[3*1536 + idx];
            const int dd = idx % D_;
            const int ri = (idx / D_) & 7;
            const int bl = idx / (8 * D_);
            const int b = b0 + h * 4 + bl;
            const int r = r0 + ri;
            g_scratch[ls * OUTSZ + (b * R_ + r) * D_ + dd] = s;
        }
        __syncthreads();
    }

    // ---- last CTA of (bg,rg) reduces the 8 l-slices and writes out ----
    __threadfence();
    if (tid == 0) {
        const int old = atomicAdd(&g_cnt[bg * 8 + rg], 1);
        s_last = (old == 7);
    }
    __syncthreads();
    if (!s_last) return;
    if (tid == 0) g_cnt[bg * 8 + rg] = 0;   // reset for next graph replay
    __threadfence();

    // 8b x 8r x 48d = 3072 outputs = 768 float4 quads; 4 per thread
#pragma unroll
    for (int s4 = 0; s4 < 4; s4++) {
        const int u  = tid + s4 * 192;      // 0..767
        const int dq = u % 12;
        const int r  = (u / 12) % 8 + r0;
        const int b  = u / 96 + b0;
        const int idx = (b * R_ + r) * D_ + dq * 4;
        const float4 bv = *(const float4*)&b_v[r * D_ + dq * 4];
        float4 s;
        s.x = 128.0f * bv.x; s.y = 128.0f * bv.y;
        s.z = 128.0f * bv.z; s.w = 128.0f * bv.w;
#pragma unroll
        for (int sl = 0; sl < 8; sl++) {
            const float4 v = *(const float4*)&g_scratch[sl * OUTSZ + idx];
            s.x += v.x; s.y += v.y; s.z += v.z; s.w += v.w;
        }
        s.x = fmaxf(s.x, 0.0f); s.y = fmaxf(s.y, 0.0f);
        s.z = fmaxf(s.z, 0.0f); s.w = fmaxf(s.w, 0.0f);
        *(float4*)&out[idx] = s;
    }
}

extern "C" void kernel_launch(void* const* d_in, const int* in_sizes, int n_in,
                              void* d_out, int out_size)
{
    const float* X     = (const float*)d_in[0];
    const float* T     = (const float*)d_in[1];
    const float* M     = (const float*)d_in[2];
    const float* DT    = (const float*)d_in[3];
    const float* P     = (const float*)d_in[4];
    const float* alpha = (const float*)d_in[5];
    const float* w_t   = (const float*)d_in[6];
    const float* b_t   = (const float*)d_in[7];
    const float* w_v   = (const float*)d_in[8];
    const float* b_v   = (const float*)d_in[9];
    float* out = (float*)d_out;

    alnn_fused<<<256, 192>>>(X, T, M, DT, P, alpha, w_t, b_t, w_v, b_v, out);
}

// round 10
// speedup vs baseline: 1.3384x; 1.1235x over previous
#include <cuda_runtime.h>

#define B_ 32
#define L_ 128
#define D_ 48
#define R_ 64
#define OUTSZ (B_*R_*D_)   // 98304

typedef unsigned long long ull;

// 8 partial slices (one per L-split) of (B,R,D)
__device__ float g_scratch[8 * OUTSZ];

#define PACK2(dst, lo, hi) \
    asm("mov.b64 %0, {%1, %2};" : "=l"(dst) : "r"(__float_as_uint(lo)), "r"(__float_as_uint(hi)))
#define UNPACK2(lo, hi, src) do { unsigned _a, _b; \
    asm("mov.b64 {%0, %1}, %2;" : "=r"(_a), "=r"(_b) : "l"(src)); \
    lo = __uint_as_float(_a); hi = __uint_as_float(_b); } while(0)
#define ADD2(d, a, b)  asm("add.rn.f32x2 %0, %1, %2;" : "=l"(d) : "l"(a), "l"(b))
#define MUL2(d, a, b)  asm("mul.rn.f32x2 %0, %1, %2;" : "=l"(d) : "l"(a), "l"(b))
#define FMA2ACC(acc, a, b) asm("fma.rn.f32x2 %0, %1, %2, %0;" : "+l"(acc) : "l"(a), "l"(b))
#define EX2(d, a)      asm("ex2.approx.ftz.f32 %0, %1;" : "=f"(d) : "f"(a))

__global__ __launch_bounds__(192, 2) void alnn_main(
    const float* __restrict__ X, const float* __restrict__ T,
    const float* __restrict__ M, const float* __restrict__ DT,
    const float* __restrict__ P, const float* __restrict__ alpha,
    const float* __restrict__ w_t, const float* __restrict__ b_t,
    const float* __restrict__ w_v)
{
    // Grid: 256 = 4 bg x 8 rg x 8 ls. Block: 192 = 4 lgroups x 48 d.
    const int c  = blockIdx.x;
    const int ls = c & 7;
    const int rg = (c >> 3) & 7;
    const int bg = c >> 6;

    const int tid = threadIdx.x;
    const int d = tid % D_;
    const int g = tid / D_;          // 0..3
    const int b0 = bg * 8;
    const int r0 = rg * 8;
    const int l0 = ls * 16 + g * 4;  // 4 l's per thread

    // Per-r constants
    float naa[8], nrr[8];
#pragma unroll
    for (int ri = 0; ri < 8; ri++) {
        const int r = r0 + ri;
        naa[ri] = -fmaxf(alpha[r], 0.0f) * 1.4426950408889634f; // -relu(alpha)*log2e
        nrr[ri] = -(float)r * (48.0f / 63.0f);
    }

    ull acc2[4][8];
#pragma unroll
    for (int p = 0; p < 4; p++)
#pragma unroll
        for (int ri = 0; ri < 8; ri++) acc2[p][ri] = 0ull;

#pragma unroll 1
    for (int j = 0; j < 4; j++) {
        const int l = l0 + j;

        // Load 8 batches at (l,d), packed into 4 b-pairs
        ull xv2[4], xr2[4], tv2[4], mv2[4], dtv2[4], pv2[4];
#pragma unroll
        for (int p = 0; p < 4; p++) {
            const int i0 = ((b0 + 2*p) * L_ + l) * D_ + d;
            const int i1 = i0 + L_ * D_;
            const float x0 = X[i0], x1 = X[i1];
            PACK2(xv2[p], x0, x1);
            const float xr0 = fmaxf(x0, 0.0f), xr1 = fmaxf(x1, 0.0f);
            PACK2(xr2[p], xr0, xr1);
            PACK2(tv2[p],  T[i0],  T[i1]);
            PACK2(mv2[p],  M[i0],  M[i1]);
            PACK2(dtv2[p], DT[i0], DT[i1]);
            PACK2(pv2[p],  P[i0],  P[i1]);
        }

        const int wbase = (r0 * L_ + l) * D_ + d;
#pragma unroll
        for (int ri = 0; ri < 8; ri++) {
            const int wi = wbase + ri * (L_ * D_);
            const float* wt = w_t + (size_t)wi * 5;
            const float w0 = wt[0], w1 = wt[1], w2 = wt[2], w3 = wt[3], w4 = wt[4];
            const float bt5 = 5.0f * b_t[wi];
            const float wvh = 0.5f * w_v[wi];       // fold relu's 1/2 into w_v (exact)
            ull w0_2, w1_2, w2_2, w3_2, w4_2, bt2, wv2, rr2, aa2;
            PACK2(w0_2, w0, w0);  PACK2(w1_2, w1, w1);
            PACK2(w2_2, w2, w2);  PACK2(w3_2, w3, w3);
            PACK2(w4_2, w4, w4);  PACK2(bt2, bt5, bt5);
            PACK2(wv2, wvh, wvh);
            PACK2(rr2, nrr[ri], nrr[ri]);
            PACK2(aa2, naa[ri], naa[ri]);

#pragma unroll
            for (int p = 0; p < 4; p++) {
                ull d2, m2, k2, i2, s2, hs2;
                ADD2(d2, tv2[p], rr2);                 // t - ref
                MUL2(m2, d2, aa2);                     // -a*(t-ref), sign varies
                ull arg2 = m2 | 0x8000000080000000ull; // -|a*(t-ref)|  (a>=0)
                float e0, e1, k0, k1;
                UNPACK2(e0, e1, arg2);
                EX2(k0, e0); EX2(k1, e1);
                PACK2(k2, k0, k1);
                MUL2(i2, xr2[p], k2);                  // relu(x)*kernel = relu(x*kernel)
                s2 = bt2;
                FMA2ACC(s2, w0_2, xv2[p]);
                FMA2ACC(s2, w1_2, i2);
                FMA2ACC(s2, w2_2, mv2[p]);
                FMA2ACC(s2, w3_2, dtv2[p]);
                FMA2ACC(s2, w4_2, pv2[p]);
                const ull ab2 = s2 & 0x7fffffff7fffffffull;
                ADD2(hs2, s2, ab2);                    // 2*relu(s)
                FMA2ACC(acc2[p][ri], wv2, hs2);        // (w_v/2)*2*relu(s)
            }
        }
    }

    // Intra-CTA reduction over the 4 l-groups, in 2 halves of 4 batches.
    __shared__ float sm[4 * 4 * 8 * D_];   // [g][bl][ri][d] = 24KB
#pragma unroll 1
    for (int h = 0; h < 2; h++) {
#pragma unroll
        for (int bl = 0; bl < 4; bl++) {
            const int p = h * 2 + (bl >> 1);
            const int hi = bl & 1;
#pragma unroll
            for (int ri = 0; ri < 8; ri++) {
                float lo, hv;
                UNPACK2(lo, hv, acc2[p][ri]);
                sm[((g * 4 + bl) * 8 + ri) * D_ + d] = hi ? hv : lo;
            }
        }
        __syncthreads();
#pragma unroll
        for (int k = 0; k < 8; k++) {
            const int idx = k * 192 + tid;             // 0..1535
            const float s = sm[idx] + sm[1536 + idx] + sm[2*1536 + idx] + sm[3*1536 + idx];
            const int dd = idx % D_;
            const int ri = (idx / D_) % 8;
            const int bl = idx / (8 * D_);
            const int b = b0 + h * 4 + bl;
            const int r = r0 + ri;
            g_scratch[ls * OUTSZ + (b * R_ + r) * D_ + dd] = s;
        }
        __syncthreads();
    }
}

// One thread per output float4: 8 independent slice loads (L2-hot) + b_v + store.
__global__ __launch_bounds__(128) void alnn_finalize(
    const float* __restrict__ b_v, float* __restrict__ out)
{
    const int q = blockIdx.x * blockDim.x + threadIdx.x;   // 0..24575
    const int dq = q % 12;
    const int r  = (q / 12) & (R_ - 1);

    const float4 bv = *(const float4*)&b_v[r * D_ + dq * 4];
    float4 s;
    s.x = 128.0f * bv.x; s.y = 128.0f * bv.y;
    s.z = 128.0f * bv.z; s.w = 128.0f * bv.w;
#pragma unroll
    for (int sl = 0; sl < 8; sl++) {
        const float4 v = *(const float4*)&g_scratch[sl * OUTSZ + q * 4];
        s.x += v.x; s.y += v.y; s.z += v.z; s.w += v.w;
    }
    s.x = fmaxf(s.x, 0.0f); s.y = fmaxf(s.y, 0.0f);
    s.z = fmaxf(s.z, 0.0f); s.w = fmaxf(s.w, 0.0f);
    *(float4*)&out[q * 4] = s;
}

extern "C" void kernel_launch(void* const* d_in, const int* in_sizes, int n_in,
                              void* d_out, int out_size)
{
    const float* X     = (const float*)d_in[0];
    const float* T     = (const float*)d_in[1];
    const float* M     = (const float*)d_in[2];
    const float* DT    = (const float*)d_in[3];
    const float* P     = (const float*)d_in[4];
    const float* alpha = (const float*)d_in[5];
    const float* w_t   = (const float*)d_in[6];
    const float* b_t   = (const float*)d_in[7];
    const float* w_v   = (const float*)d_in[8];
    const float* b_v   = (const float*)d_in[9];
    float* out = (float*)d_out;

    alnn_main<<<256, 192>>>(X, T, M, DT, P, alpha, w_t, b_t, w_v);
    alnn_finalize<<<(OUTSZ / 4) / 128, 128>>>(b_v, out);
}